// round 6
// baseline (speedup 1.0000x reference)
#include <cuda_runtime.h>
#include <cstdint>

#define NNODE 50000
#define NEDGE 800000
#define EPS_LN 1e-5f
#define EDGE_TILES32 25000   // 800000/32
#define NODE_TILES32 1563    // ceil(50000/32)
#define NTHREADS 256
#define NTEAMS 2

__device__ __align__(16) float g_Pa[NNODE*128];
__device__ __align__(16) float g_Pb[NNODE*128];
__device__ __align__(16) float g_Pn[NNODE*128];
__device__ __align__(16) float g_agg[NNODE*128];

__device__ __forceinline__ uint32_t f2tf(float f){
    uint32_t u; asm("cvt.rna.tf32.f32 %0, %1;" : "=r"(u) : "f"(f)); return u;
}
__device__ __forceinline__ float sigl(float v){ return v * (1.0f/(1.0f + __expf(-v))); }

#define TBAR(id) asm volatile("bar.sync %0, 128;" :: "r"(id) : "memory")

__device__ __forceinline__ void mma8(float* d, const uint32_t* a, uint32_t b0, uint32_t b1){
    asm volatile("mma.sync.aligned.m16n8k8.row.col.f32.tf32.tf32.f32 "
        "{%0,%1,%2,%3}, {%4,%5,%6,%7}, {%8,%9}, {%0,%1,%2,%3};"
        : "+f"(d[0]), "+f"(d[1]), "+f"(d[2]), "+f"(d[3])
        : "r"(a[0]), "r"(a[1]), "r"(a[2]), "r"(a[3]), "r"(b0), "r"(b1));
}

// W[k][n] row-major [128,128] -> SMEM fragment order, tf32-rounded.
__device__ void load_wfrag(const float* __restrict__ W, float* __restrict__ dst,
                           int tid, int nthr){
    for (int idx = tid; idx < 16384; idx += nthr){
        int q = idx & 3, lane = (idx >> 2) & 31, kpair = (idx >> 7) & 7, ntile = idx >> 10;
        int tig = lane & 3, g = lane >> 2;
        int kstep = kpair * 2 + (q >> 1);
        int k = kstep * 8 + tig + (q & 1) * 4;
        int n = ntile * 8 + g;
        dst[idx] = __uint_as_float(f2tf(W[k * 128 + n]));
    }
}

// A buffer: 32 rows x 128 floats, XOR-swizzled granules of 4 floats.
// addr(row, k) = row*128 + (((k>>2) ^ (row&7))<<2) + (k&3)
template<bool GUARD>
__device__ __forceinline__ void stage32(const float* __restrict__ src, float* __restrict__ Ab,
                                        int tt, int nvalid){
    const float4* s4 = (const float4*)src;
    #pragma unroll
    for (int rep = 0; rep < 8; rep++){
        int idx = tt + rep * 128;          // 0..1023
        int row = idx >> 5, g4 = idx & 31;
        float4 v;
        if (GUARD && row >= nvalid) v = make_float4(0.f,0.f,0.f,0.f);
        else v = s4[idx];
        *(float4*)(Ab + row * 128 + (((g4 ^ (row & 7)) << 2))) = v;
    }
}

// acc[rt][nt][0..3]: 32 rows (2 row-tiles of m16) x warp's 32 cols
__device__ __forceinline__ void gemm32(const float* __restrict__ Ab,
                                       const float* __restrict__ sWf,
                                       int wt, int lane, float acc[2][4][4]){
    const int g = lane >> 2, tig = lane & 3;
    #pragma unroll
    for (int rt = 0; rt < 2; rt++)
        #pragma unroll
        for (int nt = 0; nt < 4; nt++)
            #pragma unroll
            for (int j = 0; j < 4; j++) acc[rt][nt][j] = 0.f;
    #pragma unroll
    for (int kp = 0; kp < 8; kp++){
        uint32_t af[2][2][4];
        #pragma unroll
        for (int rt = 0; rt < 2; rt++){
            const int r0 = rt*16 + g, r1 = r0 + 8;
            const int s0 = r0 & 7;      // == r1 & 7
            #pragma unroll
            for (int h = 0; h < 2; h++){
                int ga = (kp*4 + 2*h) ^ s0, gb = (kp*4 + 2*h + 1) ^ s0;
                af[rt][h][0] = __float_as_uint(Ab[r0*128 + (ga<<2) + tig]);
                af[rt][h][1] = __float_as_uint(Ab[r1*128 + (ga<<2) + tig]);
                af[rt][h][2] = __float_as_uint(Ab[r0*128 + (gb<<2) + tig]);
                af[rt][h][3] = __float_as_uint(Ab[r1*128 + (gb<<2) + tig]);
            }
        }
        #pragma unroll
        for (int nt = 0; nt < 4; nt++){
            float4 w = ((const float4*)sWf)[((wt*4 + nt)*8 + kp)*32 + lane];
            #pragma unroll
            for (int rt = 0; rt < 2; rt++){
                mma8(acc[rt][nt], af[rt][0], __float_as_uint(w.x), __float_as_uint(w.y));
                mma8(acc[rt][nt], af[rt][1], __float_as_uint(w.z), __float_as_uint(w.w));
            }
        }
    }
}

// swizzled float2 store into A buffer at (row, col), col = wt*32+nt*8+tig*2
__device__ __forceinline__ void ab_st2(float* __restrict__ Ab, int row, int gran, int off, float2 v){
    *(float2*)(Ab + row*128 + (((gran ^ (row & 7)) << 2)) + off) = v;
}

// ------------------------------------------------------------------ kernel 1
__global__ void __launch_bounds__(NTHREADS, 1) pre_kernel(
    const float* __restrict__ x,
    const float* __restrict__ ew1, const float* __restrict__ eb1,
    const float* __restrict__ nw1, const float* __restrict__ nb1)
{
    extern __shared__ float sm[];
    float* sW0 = sm;
    float* sW1 = sm + 16384;
    float* sW2 = sm + 32768;
    float* sB  = sm + 49152;    // eb1 | nb1 (256)
    float* sA  = sm + 49408;    // 2 teams * 32*128

    const int tid = threadIdx.x;
    load_wfrag(ew1,         sW0, tid, NTHREADS);
    load_wfrag(ew1 + 16384, sW1, tid, NTHREADS);
    load_wfrag(nw1,         sW2, tid, NTHREADS);
    if (tid < 128){ sB[tid] = eb1[tid]; sB[128 + tid] = nb1[tid]; }
    __syncthreads();

    const int wid = tid >> 5, lane = tid & 31, team = wid >> 2, wt = wid & 3;
    const int g = lane >> 2, tig = lane & 3, tt = tid & 127, bid = 1 + team;
    float* Ab = sA + team * 4096;

    for (int tile = blockIdx.x * NTEAMS + team; tile < NODE_TILES32; tile += gridDim.x * NTEAMS){
        const int n0 = tile * 32;
        const int nvalid = (NNODE - n0 < 32) ? (NNODE - n0) : 32;
        TBAR(bid);
        stage32<true>(x + (size_t)n0 * 128, Ab, tt, nvalid);
        TBAR(bid);

        float acc[2][4][4];
        #pragma unroll
        for (int L = 0; L < 3; L++){
            gemm32(Ab, (L==0)?sW0:((L==1)?sW1:sW2), wt, lane, acc);
            float* dst = (L==0) ? g_Pa : ((L==1) ? g_Pb : g_Pn);
            const float* bias = (L==0) ? sB : ((L==2) ? sB + 128 : nullptr);
            #pragma unroll
            for (int rt = 0; rt < 2; rt++){
                const int rA = n0 + rt*16 + g, rB = rA + 8;
                #pragma unroll
                for (int nt = 0; nt < 4; nt++){
                    int col = wt*32 + nt*8 + tig*2;
                    float b0 = bias ? bias[col] : 0.f, b1 = bias ? bias[col+1] : 0.f;
                    float2 oA = { acc[rt][nt][0] + b0, acc[rt][nt][1] + b1 };
                    float2 oB = { acc[rt][nt][2] + b0, acc[rt][nt][3] + b1 };
                    if (rA < NNODE) *(float2*)(dst + (size_t)rA * 128 + col) = oA;
                    if (rB < NNODE) *(float2*)(dst + (size_t)rB * 128 + col) = oB;
                }
            }
        }
    }
}

// ------------------------------------------------------------------ kernel 2
__global__ void __launch_bounds__(NTHREADS, 1) edge_kernel(
    const int* __restrict__ ei, const float* __restrict__ ea,
    const float* __restrict__ ew1, const float* __restrict__ ew2, const float* __restrict__ ew3,
    const float* __restrict__ eb2, const float* __restrict__ eb3,
    const float* __restrict__ elg, const float* __restrict__ elb,
    float* __restrict__ outE)
{
    extern __shared__ float sm[];
    float* sW1 = sm;
    float* sW2 = sm + 16384;
    float* sW3 = sm + 32768;
    float* sB  = sm + 49152;    // eb2|eb3|gamma|beta (512)
    float* sRed= sm + 49664;    // 256: [team][warp][rowlocal]
    float* sA  = sm + 49920;    // 2 * 4096

    const int tid = threadIdx.x;
    load_wfrag(ew1 + 32768, sW1, tid, NTHREADS);
    load_wfrag(ew2,         sW2, tid, NTHREADS);
    load_wfrag(ew3,         sW3, tid, NTHREADS);
    if (tid < 128){
        sB[tid] = eb2[tid]; sB[128+tid] = eb3[tid]; sB[256+tid] = elg[tid]; sB[384+tid] = elb[tid];
    }
    __syncthreads();

    const int wid = tid >> 5, lane = tid & 31, team = wid >> 2, wt = wid & 3;
    const int g = lane >> 2, tig = lane & 3, tt = tid & 127, bid = 1 + team;
    float* Ab = sA + team * 4096;
    float* sR = sRed + team * 128;

    for (int tile = blockIdx.x * NTEAMS + team; tile < EDGE_TILES32; tile += gridDim.x * NTEAMS){
        const int e0 = tile * 32;
        TBAR(bid);
        stage32<false>(ea + (size_t)e0 * 128, Ab, tt, 32);
        TBAR(bid);

        int er[4], vi[4], vj[4];
        #pragma unroll
        for (int r = 0; r < 4; r++){
            er[r] = e0 + (r>>1)*16 + g + (r&1)*8;
            vi[r] = ei[er[r]];
            vj[r] = ei[NEDGE + er[r]];
        }

        float acc[2][4][4];
        // ---- layer 1: ea @ W1c, + Pa[i] + Pb[j], silu -> Ab
        gemm32(Ab, sW1, wt, lane, acc);
        TBAR(bid);
        #pragma unroll
        for (int rt = 0; rt < 2; rt++){
            #pragma unroll
            for (int nt = 0; nt < 4; nt++){
                int col = wt*32 + nt*8 + tig*2;
                int gran = wt*8 + nt*2 + (tig>>1), off = (tig&1)*2;
                float2 paA = *(const float2*)(g_Pa + (size_t)vi[rt*2  ]*128 + col);
                float2 pbA = *(const float2*)(g_Pb + (size_t)vj[rt*2  ]*128 + col);
                float2 paB = *(const float2*)(g_Pa + (size_t)vi[rt*2+1]*128 + col);
                float2 pbB = *(const float2*)(g_Pb + (size_t)vj[rt*2+1]*128 + col);
                float2 wA = { __uint_as_float(f2tf(sigl(acc[rt][nt][0] + paA.x + pbA.x))),
                              __uint_as_float(f2tf(sigl(acc[rt][nt][1] + paA.y + pbA.y))) };
                float2 wB = { __uint_as_float(f2tf(sigl(acc[rt][nt][2] + paB.x + pbB.x))),
                              __uint_as_float(f2tf(sigl(acc[rt][nt][3] + paB.y + pbB.y))) };
                ab_st2(Ab, rt*16 + g,     gran, off, wA);
                ab_st2(Ab, rt*16 + g + 8, gran, off, wB);
            }
        }
        TBAR(bid);
        // ---- layer 2: + eb2, silu -> Ab
        gemm32(Ab, sW2, wt, lane, acc);
        TBAR(bid);
        #pragma unroll
        for (int rt = 0; rt < 2; rt++){
            #pragma unroll
            for (int nt = 0; nt < 4; nt++){
                int col = wt*32 + nt*8 + tig*2;
                int gran = wt*8 + nt*2 + (tig>>1), off = (tig&1)*2;
                float b0 = sB[col], b1 = sB[col+1];
                float2 wA = { __uint_as_float(f2tf(sigl(acc[rt][nt][0] + b0))),
                              __uint_as_float(f2tf(sigl(acc[rt][nt][1] + b1))) };
                float2 wB = { __uint_as_float(f2tf(sigl(acc[rt][nt][2] + b0))),
                              __uint_as_float(f2tf(sigl(acc[rt][nt][3] + b1))) };
                ab_st2(Ab, rt*16 + g,     gran, off, wA);
                ab_st2(Ab, rt*16 + g + 8, gran, off, wB);
            }
        }
        TBAR(bid);
        // ---- layer 3: + eb3, LN, residual, scatter
        gemm32(Ab, sW3, wt, lane, acc);
        float s[4], qq[4];
        #pragma unroll
        for (int r = 0; r < 4; r++){ s[r] = 0.f; qq[r] = 0.f; }
        #pragma unroll
        for (int rt = 0; rt < 2; rt++)
            #pragma unroll
            for (int nt = 0; nt < 4; nt++){
                int col = wt*32 + nt*8 + tig*2;
                acc[rt][nt][0] += sB[128+col]; acc[rt][nt][1] += sB[128+col+1];
                acc[rt][nt][2] += sB[128+col]; acc[rt][nt][3] += sB[128+col+1];
                s[rt*2  ] += acc[rt][nt][0] + acc[rt][nt][1];
                s[rt*2+1] += acc[rt][nt][2] + acc[rt][nt][3];
                qq[rt*2  ] += acc[rt][nt][0]*acc[rt][nt][0] + acc[rt][nt][1]*acc[rt][nt][1];
                qq[rt*2+1] += acc[rt][nt][2]*acc[rt][nt][2] + acc[rt][nt][3]*acc[rt][nt][3];
            }
        #pragma unroll
        for (int o = 1; o < 4; o <<= 1)
            #pragma unroll
            for (int r = 0; r < 4; r++){
                s[r]  += __shfl_xor_sync(0xffffffffu, s[r],  o);
                qq[r] += __shfl_xor_sync(0xffffffffu, qq[r], o);
            }
        if (tig == 0)
            #pragma unroll
            for (int r = 0; r < 4; r++)
                sR[wt*32 + (r>>1)*16 + g + (r&1)*8] = s[r];
        TBAR(bid);
        float mean[4], inv[4];
        #pragma unroll
        for (int r = 0; r < 4; r++){
            int rl = (r>>1)*16 + g + (r&1)*8;
            float t = sR[rl] + sR[32+rl] + sR[64+rl] + sR[96+rl];
            mean[r] = t * (1.f/128.f);
        }
        TBAR(bid);
        if (tig == 0)
            #pragma unroll
            for (int r = 0; r < 4; r++)
                sR[wt*32 + (r>>1)*16 + g + (r&1)*8] = qq[r];
        TBAR(bid);
        #pragma unroll
        for (int r = 0; r < 4; r++){
            int rl = (r>>1)*16 + g + (r&1)*8;
            float t = sR[rl] + sR[32+rl] + sR[64+rl] + sR[96+rl];
            inv[r] = rsqrtf(t * (1.f/128.f) - mean[r]*mean[r] + EPS_LN);
        }
        #pragma unroll
        for (int rt = 0; rt < 2; rt++)
            #pragma unroll
            for (int nt = 0; nt < 4; nt++){
                int col = wt*32 + nt*8 + tig*2;
                float gm0 = sB[256+col], gm1 = sB[256+col+1];
                float bt0 = sB[384+col], bt1 = sB[384+col+1];
                #pragma unroll
                for (int h = 0; h < 2; h++){     // h=0: row rA (acc 0,1); h=1: row rB (acc 2,3)
                    int r = rt*2 + h;
                    float2 rv = *(const float2*)(ea + (size_t)er[r]*128 + col);
                    float2 o = { rv.x + (acc[rt][nt][2*h  ] - mean[r])*inv[r]*gm0 + bt0,
                                 rv.y + (acc[rt][nt][2*h+1] - mean[r])*inv[r]*gm1 + bt1 };
                    *(float2*)(outE + (size_t)er[r]*128 + col) = o;
                    asm volatile("red.global.add.v2.f32 [%0], {%1,%2};"
                                 :: "l"(g_agg + (size_t)vj[r]*128 + col), "f"(o.x), "f"(o.y) : "memory");
                }
            }
    }
}

// ------------------------------------------------------------------ kernel 3
__global__ void __launch_bounds__(NTHREADS, 1) node_kernel(
    const float* __restrict__ x,
    const float* __restrict__ nw1, const float* __restrict__ nw2, const float* __restrict__ nw3,
    const float* __restrict__ nb2, const float* __restrict__ nb3,
    const float* __restrict__ nlg, const float* __restrict__ nlb,
    float* __restrict__ outX)
{
    extern __shared__ float sm[];
    float* sW1 = sm;
    float* sW2 = sm + 16384;
    float* sW3 = sm + 32768;
    float* sB  = sm + 49152;
    float* sRed= sm + 49664;
    float* sA  = sm + 49920;

    const int tid = threadIdx.x;
    load_wfrag(nw1 + 16384, sW1, tid, NTHREADS);
    load_wfrag(nw2,         sW2, tid, NTHREADS);
    load_wfrag(nw3,         sW3, tid, NTHREADS);
    if (tid < 128){
        sB[tid] = nb2[tid]; sB[128+tid] = nb3[tid]; sB[256+tid] = nlg[tid]; sB[384+tid] = nlb[tid];
    }
    __syncthreads();

    const int wid = tid >> 5, lane = tid & 31, team = wid >> 2, wt = wid & 3;
    const int g = lane >> 2, tig = lane & 3, tt = tid & 127, bid = 1 + team;
    float* Ab = sA + team * 4096;
    float* sR = sRed + team * 128;

    for (int tile = blockIdx.x * NTEAMS + team; tile < NODE_TILES32; tile += gridDim.x * NTEAMS){
        const int n0 = tile * 32;
        const int nvalid = (NNODE - n0 < 32) ? (NNODE - n0) : 32;
        TBAR(bid);
        stage32<true>(g_agg + (size_t)n0 * 128, Ab, tt, nvalid);
        TBAR(bid);

        int rr[4];
        #pragma unroll
        for (int r = 0; r < 4; r++){
            int rowg = n0 + (r>>1)*16 + g + (r&1)*8;
            rr[r] = rowg < NNODE ? rowg : NNODE - 1;
        }

        float acc[2][4][4];
        gemm32(Ab, sW1, wt, lane, acc);
        TBAR(bid);
        #pragma unroll
        for (int rt = 0; rt < 2; rt++){
            #pragma unroll
            for (int nt = 0; nt < 4; nt++){
                int col = wt*32 + nt*8 + tig*2;
                int gran = wt*8 + nt*2 + (tig>>1), off = (tig&1)*2;
                float2 pnA = *(const float2*)(g_Pn + (size_t)rr[rt*2  ]*128 + col);
                float2 pnB = *(const float2*)(g_Pn + (size_t)rr[rt*2+1]*128 + col);
                float2 wA = { __uint_as_float(f2tf(sigl(acc[rt][nt][0] + pnA.x))),
                              __uint_as_float(f2tf(sigl(acc[rt][nt][1] + pnA.y))) };
                float2 wB = { __uint_as_float(f2tf(sigl(acc[rt][nt][2] + pnB.x))),
                              __uint_as_float(f2tf(sigl(acc[rt][nt][3] + pnB.y))) };
                ab_st2(Ab, rt*16 + g,     gran, off, wA);
                ab_st2(Ab, rt*16 + g + 8, gran, off, wB);
            }
        }
        TBAR(bid);
        gemm32(Ab, sW2, wt, lane, acc);
        TBAR(bid);
        #pragma unroll
        for (int rt = 0; rt < 2; rt++){
            #pragma unroll
            for (int nt = 0; nt < 4; nt++){
                int col = wt*32 + nt*8 + tig*2;
                int gran = wt*8 + nt*2 + (tig>>1), off = (tig&1)*2;
                float b0 = sB[col], b1 = sB[col+1];
                float2 wA = { __uint_as_float(f2tf(sigl(acc[rt][nt][0] + b0))),
                              __uint_as_float(f2tf(sigl(acc[rt][nt][1] + b1))) };
                float2 wB = { __uint_as_float(f2tf(sigl(acc[rt][nt][2] + b0))),
                              __uint_as_float(f2tf(sigl(acc[rt][nt][3] + b1))) };
                ab_st2(Ab, rt*16 + g,     gran, off, wA);
                ab_st2(Ab, rt*16 + g + 8, gran, off, wB);
            }
        }
        TBAR(bid);
        gemm32(Ab, sW3, wt, lane, acc);
        float s[4], qq[4];
        #pragma unroll
        for (int r = 0; r < 4; r++){ s[r] = 0.f; qq[r] = 0.f; }
        #pragma unroll
        for (int rt = 0; rt < 2; rt++)
            #pragma unroll
            for (int nt = 0; nt < 4; nt++){
                int col = wt*32 + nt*8 + tig*2;
                acc[rt][nt][0] += sB[128+col]; acc[rt][nt][1] += sB[128+col+1];
                acc[rt][nt][2] += sB[128+col]; acc[rt][nt][3] += sB[128+col+1];
                s[rt*2  ] += acc[rt][nt][0] + acc[rt][nt][1];
                s[rt*2+1] += acc[rt][nt][2] + acc[rt][nt][3];
                qq[rt*2  ] += acc[rt][nt][0]*acc[rt][nt][0] + acc[rt][nt][1]*acc[rt][nt][1];
                qq[rt*2+1] += acc[rt][nt][2]*acc[rt][nt][2] + acc[rt][nt][3]*acc[rt][nt][3];
            }
        #pragma unroll
        for (int o = 1; o < 4; o <<= 1)
            #pragma unroll
            for (int r = 0; r < 4; r++){
                s[r]  += __shfl_xor_sync(0xffffffffu, s[r],  o);
                qq[r] += __shfl_xor_sync(0xffffffffu, qq[r], o);
            }
        if (tig == 0)
            #pragma unroll
            for (int r = 0; r < 4; r++)
                sR[wt*32 + (r>>1)*16 + g + (r&1)*8] = s[r];
        TBAR(bid);
        float mean[4], inv[4];
        #pragma unroll
        for (int r = 0; r < 4; r++){
            int rl = (r>>1)*16 + g + (r&1)*8;
            float t = sR[rl] + sR[32+rl] + sR[64+rl] + sR[96+rl];
            mean[r] = t * (1.f/128.f);
        }
        TBAR(bid);
        if (tig == 0)
            #pragma unroll
            for (int r = 0; r < 4; r++)
                sR[wt*32 + (r>>1)*16 + g + (r&1)*8] = qq[r];
        TBAR(bid);
        #pragma unroll
        for (int r = 0; r < 4; r++){
            int rl = (r>>1)*16 + g + (r&1)*8;
            float t = sR[rl] + sR[32+rl] + sR[64+rl] + sR[96+rl];
            inv[r] = rsqrtf(t * (1.f/128.f) - mean[r]*mean[r] + EPS_LN);
        }
        #pragma unroll
        for (int rt = 0; rt < 2; rt++)
            #pragma unroll
            for (int nt = 0; nt < 4; nt++){
                int col = wt*32 + nt*8 + tig*2;
                float gm0 = sB[256+col], gm1 = sB[256+col+1];
                float bt0 = sB[384+col], bt1 = sB[384+col+1];
                #pragma unroll
                for (int h = 0; h < 2; h++){
                    int r = rt*2 + h;
                    int rowg = n0 + (r>>1)*16 + g + (r&1)*8;
                    float2 rv = *(const float2*)(x + (size_t)rr[r]*128 + col);
                    float2 o = { rv.x + (acc[rt][nt][2*h  ] - mean[r])*inv[r]*gm0 + bt0,
                                 rv.y + (acc[rt][nt][2*h+1] - mean[r])*inv[r]*gm1 + bt1 };
                    if (rowg < NNODE)
                        *(float2*)(outX + (size_t)rowg*128 + col) = o;
                }
            }
    }
}

// ------------------------------------------------------------------ host
extern "C" void kernel_launch(void* const* d_in, const int* in_sizes, int n_in,
                              void* d_out, int out_size) {
    const float* x   = (const float*)d_in[0];
    const int*   ei  = (const int*)  d_in[1];
    const float* ea  = (const float*)d_in[2];
    const float* ew1 = (const float*)d_in[3];
    const float* eb1 = (const float*)d_in[4];
    const float* ew2 = (const float*)d_in[5];
    const float* eb2 = (const float*)d_in[6];
    const float* ew3 = (const float*)d_in[7];
    const float* eb3 = (const float*)d_in[8];
    const float* elg = (const float*)d_in[9];
    const float* elb = (const float*)d_in[10];
    const float* nw1 = (const float*)d_in[11];
    const float* nb1 = (const float*)d_in[12];
    const float* nw2 = (const float*)d_in[13];
    const float* nb2 = (const float*)d_in[14];
    const float* nw3 = (const float*)d_in[15];
    const float* nb3 = (const float*)d_in[16];
    const float* nlg = (const float*)d_in[17];
    const float* nlb = (const float*)d_in[18];

    float* outX = (float*)d_out;
    float* outE = outX + (size_t)NNODE * 128;

    // pre:  (49152 + 256 + 8192) * 4        = 230400
    // main: (49152 + 512 + 256 + 8192) * 4  = 232448 (== 227KB opt-in max)
    const size_t smem_pre  = 230400;
    const size_t smem_main = 232448;
    cudaFuncSetAttribute(pre_kernel,  cudaFuncAttributeMaxDynamicSharedMemorySize, (int)smem_pre);
    cudaFuncSetAttribute(edge_kernel, cudaFuncAttributeMaxDynamicSharedMemorySize, (int)smem_main);
    cudaFuncSetAttribute(node_kernel, cudaFuncAttributeMaxDynamicSharedMemorySize, (int)smem_main);

    void* aggp = nullptr;
    cudaGetSymbolAddress(&aggp, g_agg);
    cudaMemsetAsync(aggp, 0, sizeof(float) * (size_t)NNODE * 128, 0);

    pre_kernel<<<152, NTHREADS, smem_pre>>>(x, ew1, eb1, nw1, nb1);
    edge_kernel<<<152, NTHREADS, smem_main>>>(ei, ea, ew1, ew2, ew3, eb2, eb3, elg, elb, outE);
    node_kernel<<<152, NTHREADS, smem_main>>>(x, nw1, nw2, nw3, nb2, nb3, nlg, nlb, outX);
}

// round 7
// speedup vs baseline: 1.2278x; 1.2278x over previous
#include <cuda_runtime.h>
#include <cstdint>

#define NNODE 50000
#define NEDGE 800000
#define EPS_LN 1e-5f
#define EDGE_TTILES 50000   // 800000/16
#define NODE_TTILES 3125    // 50000/16
#define ASTRIDE 132
#define NTHREADS 384
#define NTEAMS 3

__device__ __align__(16) float g_Pa[NNODE*128];
__device__ __align__(16) float g_Pb[NNODE*128];
__device__ __align__(16) float g_Pn[NNODE*128];
__device__ __align__(16) float g_agg[NNODE*128];

__device__ __forceinline__ uint32_t f2tf(float f){
    uint32_t u; asm("cvt.rna.tf32.f32 %0, %1;" : "=r"(u) : "f"(f)); return u;
}
__device__ __forceinline__ float sigl(float v){ return v * (1.0f/(1.0f + __expf(-v))); }

#define TBAR(id) asm volatile("bar.sync %0, 128;" :: "r"(id) : "memory")

__device__ __forceinline__ void mma8(float* d, const uint32_t* a, uint32_t b0, uint32_t b1){
    asm volatile("mma.sync.aligned.m16n8k8.row.col.f32.tf32.tf32.f32 "
        "{%0,%1,%2,%3}, {%4,%5,%6,%7}, {%8,%9}, {%0,%1,%2,%3};"
        : "+f"(d[0]), "+f"(d[1]), "+f"(d[2]), "+f"(d[3])
        : "r"(a[0]), "r"(a[1]), "r"(a[2]), "r"(a[3]), "r"(b0), "r"(b1));
}

// W[k][n] row-major [128,128] -> SMEM fragment order, tf32-rounded.
__device__ void load_wfrag(const float* __restrict__ W, float* __restrict__ dst,
                           int tid, int nthr){
    for (int idx = tid; idx < 16384; idx += nthr){
        int q = idx & 3, lane = (idx >> 2) & 31, kpair = (idx >> 7) & 7, ntile = idx >> 10;
        int tig = lane & 3, g = lane >> 2;
        int kstep = kpair * 2 + (q >> 1);
        int k = kstep * 8 + tig + (q & 1) * 4;
        int n = ntile * 8 + g;
        dst[idx] = __uint_as_float(f2tf(W[k * 128 + n]));
    }
}

// acc[nt][0..3] = (16x128 A in SMEM) x (128x128 W frag), warp owns cols wt*32..+31
__device__ __forceinline__ void gemm_layer(const float* __restrict__ Ab,
                                           const float* __restrict__ sWf,
                                           int wt, int lane, float acc[4][4]){
    const int g = lane >> 2, tig = lane & 3;
    #pragma unroll
    for (int nt = 0; nt < 4; nt++)
        #pragma unroll
        for (int j = 0; j < 4; j++) acc[nt][j] = 0.f;
    #pragma unroll
    for (int kp = 0; kp < 8; kp++){
        const int k0 = kp * 16;
        uint32_t af0[4], af1[4];
        af0[0] = __float_as_uint(Ab[ g     *ASTRIDE + k0 + tig    ]);
        af0[1] = __float_as_uint(Ab[(g+8)  *ASTRIDE + k0 + tig    ]);
        af0[2] = __float_as_uint(Ab[ g     *ASTRIDE + k0 + tig + 4]);
        af0[3] = __float_as_uint(Ab[(g+8)  *ASTRIDE + k0 + tig + 4]);
        af1[0] = __float_as_uint(Ab[ g     *ASTRIDE + k0 + 8 + tig    ]);
        af1[1] = __float_as_uint(Ab[(g+8)  *ASTRIDE + k0 + 8 + tig    ]);
        af1[2] = __float_as_uint(Ab[ g     *ASTRIDE + k0 + 8 + tig + 4]);
        af1[3] = __float_as_uint(Ab[(g+8)  *ASTRIDE + k0 + 8 + tig + 4]);
        #pragma unroll
        for (int nt = 0; nt < 4; nt++){
            float4 w = ((const float4*)sWf)[((wt*4 + nt)*8 + kp)*32 + lane];
            mma8(acc[nt], af0, __float_as_uint(w.x), __float_as_uint(w.y));
            mma8(acc[nt], af1, __float_as_uint(w.z), __float_as_uint(w.w));
        }
    }
}

__device__ __forceinline__ void stage16(const float* __restrict__ src, float* __restrict__ Ab,
                                        int tt){
    const float4* s4 = (const float4*)src;
    #pragma unroll
    for (int rep = 0; rep < 4; rep++){
        int idx = tt + rep * 128;
        int row = idx >> 5, c4 = idx & 31;
        float4 v = s4[idx];
        *(float4*)(Ab + row * ASTRIDE + c4 * 4) = v;
    }
}

// ------------------------------------------------------------------ kernel 1
__global__ void __launch_bounds__(NTHREADS, 1) pre_kernel(
    const float* __restrict__ x,
    const float* __restrict__ ew1, const float* __restrict__ eb1,
    const float* __restrict__ nw1, const float* __restrict__ nb1)
{
    extern __shared__ float sm[];
    float* sW0 = sm;
    float* sW1 = sm + 16384;
    float* sW2 = sm + 32768;
    float* sB  = sm + 49152;    // eb1 | nb1
    float* sA  = sm + 49408;    // NTEAMS * 16*132

    const int tid = threadIdx.x;
    load_wfrag(ew1,         sW0, tid, NTHREADS);
    load_wfrag(ew1 + 16384, sW1, tid, NTHREADS);
    load_wfrag(nw1,         sW2, tid, NTHREADS);
    if (tid < 128){ sB[tid] = eb1[tid]; sB[128 + tid] = nb1[tid]; }
    __syncthreads();

    const int wid = tid >> 5, lane = tid & 31, team = wid >> 2, wt = wid & 3;
    const int g = lane >> 2, tig = lane & 3, tt = tid & 127, bid = 1 + team;
    float* Ab = sA + team * (16 * ASTRIDE);

    for (int tile = blockIdx.x * NTEAMS + team; tile < NODE_TTILES; tile += gridDim.x * NTEAMS){
        const int n0 = tile * 16;
        TBAR(bid);
        stage16(x + (size_t)n0 * 128, Ab, tt);
        TBAR(bid);
        const int rA = n0 + g, rB = n0 + g + 8;

        float acc[4][4];
        #pragma unroll
        for (int L = 0; L < 3; L++){
            gemm_layer(Ab, (L==0)?sW0:((L==1)?sW1:sW2), wt, lane, acc);
            float* dst = (L==0) ? g_Pa : ((L==1) ? g_Pb : g_Pn);
            const float* bias = (L==0) ? sB : ((L==2) ? sB + 128 : nullptr);
            #pragma unroll
            for (int nt = 0; nt < 4; nt++){
                int col = wt*32 + nt*8 + tig*2;
                float b0 = bias ? bias[col] : 0.f, b1 = bias ? bias[col+1] : 0.f;
                float2 oA = { acc[nt][0] + b0, acc[nt][1] + b1 };
                float2 oB = { acc[nt][2] + b0, acc[nt][3] + b1 };
                *(float2*)(dst + (size_t)rA * 128 + col) = oA;
                *(float2*)(dst + (size_t)rB * 128 + col) = oB;
            }
        }
    }
}

// ------------------------------------------------------------------ kernel 2
__global__ void __launch_bounds__(NTHREADS, 1) edge_kernel(
    const int* __restrict__ ei, const float* __restrict__ ea,
    const float* __restrict__ ew1, const float* __restrict__ ew2, const float* __restrict__ ew3,
    const float* __restrict__ eb2, const float* __restrict__ eb3,
    const float* __restrict__ elg, const float* __restrict__ elb,
    float* __restrict__ outE)
{
    extern __shared__ float sm[];
    float* sW1 = sm;
    float* sW2 = sm + 16384;
    float* sW3 = sm + 32768;
    float* sB  = sm + 49152;    // eb2 | eb3 | gamma | beta (512)
    float* sRed= sm + 49664;    // [384]: sum[192] | ssq[192]
    float* sA  = sm + 50048;

    const int tid = threadIdx.x;
    load_wfrag(ew1 + 32768, sW1, tid, NTHREADS);
    load_wfrag(ew2,         sW2, tid, NTHREADS);
    load_wfrag(ew3,         sW3, tid, NTHREADS);
    if (tid < 128){
        sB[tid] = eb2[tid]; sB[128+tid] = eb3[tid]; sB[256+tid] = elg[tid]; sB[384+tid] = elb[tid];
    }
    __syncthreads();

    const int wid = tid >> 5, lane = tid & 31, team = wid >> 2, wt = wid & 3;
    const int g = lane >> 2, tig = lane & 3, tt = tid & 127, bid = 1 + team;
    float* Ab = sA + team * (16 * ASTRIDE);

    const int tstep = gridDim.x * NTEAMS;
    int tile = blockIdx.x * NTEAMS + team;

    // --- first-tile prefetch (ea rows + indices) into registers
    float4 pf[4];
    int pviA = 0, pvjA = 0, pviB = 0, pvjB = 0;
    if (tile < EDGE_TTILES){
        const float4* s4 = (const float4*)(ea + (size_t)tile * 16 * 128);
        #pragma unroll
        for (int rep = 0; rep < 4; rep++) pf[rep] = s4[tt + rep * 128];
        pviA = ei[tile*16 + g];         pvjA = ei[NEDGE + tile*16 + g];
        pviB = ei[tile*16 + g + 8];     pvjB = ei[NEDGE + tile*16 + g + 8];
    }

    for (; tile < EDGE_TTILES; tile += tstep){
        const int e0 = tile * 16;
        TBAR(bid);
        // stage prefetched rows into Ab
        #pragma unroll
        for (int rep = 0; rep < 4; rep++){
            int idx = tt + rep * 128;
            int row = idx >> 5, c4 = idx & 31;
            *(float4*)(Ab + row * ASTRIDE + c4 * 4) = pf[rep];
        }
        TBAR(bid);

        const int eA = e0 + g, eB = e0 + g + 8;
        const int viA = pviA, vjA = pvjA, viB = pviB, vjB = pvjB;

        // --- early gathers: issue BEFORE gemm1, consume after (latency hidden by MMA)
        float2 paA[4], pbA[4], paB[4], pbB[4];
        #pragma unroll
        for (int nt = 0; nt < 4; nt++){
            int col = wt*32 + nt*8 + tig*2;
            paA[nt] = __ldg((const float2*)(g_Pa + (size_t)viA*128 + col));
            pbA[nt] = __ldg((const float2*)(g_Pb + (size_t)vjA*128 + col));
            paB[nt] = __ldg((const float2*)(g_Pa + (size_t)viB*128 + col));
            pbB[nt] = __ldg((const float2*)(g_Pb + (size_t)vjB*128 + col));
        }

        float acc[4][4];
        // ---- layer 1: ea @ W1c, + Pa[i] + Pb[j], silu
        gemm_layer(Ab, sW1, wt, lane, acc);
        TBAR(bid);
        #pragma unroll
        for (int nt = 0; nt < 4; nt++){
            int col = wt*32 + nt*8 + tig*2;
            float2 wA = { __uint_as_float(f2tf(sigl(acc[nt][0] + paA[nt].x + pbA[nt].x))),
                          __uint_as_float(f2tf(sigl(acc[nt][1] + paA[nt].y + pbA[nt].y))) };
            float2 wB = { __uint_as_float(f2tf(sigl(acc[nt][2] + paB[nt].x + pbB[nt].x))),
                          __uint_as_float(f2tf(sigl(acc[nt][3] + paB[nt].y + pbB[nt].y))) };
            *(float2*)(Ab +  g   *ASTRIDE + col) = wA;
            *(float2*)(Ab + (g+8)*ASTRIDE + col) = wB;
        }
        TBAR(bid);
        // ---- layer 2: + eb2, silu
        gemm_layer(Ab, sW2, wt, lane, acc);
        TBAR(bid);
        #pragma unroll
        for (int nt = 0; nt < 4; nt++){
            int col = wt*32 + nt*8 + tig*2;
            float b0 = sB[col], b1 = sB[col+1];
            float2 wA = { __uint_as_float(f2tf(sigl(acc[nt][0] + b0))),
                          __uint_as_float(f2tf(sigl(acc[nt][1] + b1))) };
            float2 wB = { __uint_as_float(f2tf(sigl(acc[nt][2] + b0))),
                          __uint_as_float(f2tf(sigl(acc[nt][3] + b1))) };
            *(float2*)(Ab +  g   *ASTRIDE + col) = wA;
            *(float2*)(Ab + (g+8)*ASTRIDE + col) = wB;
        }
        TBAR(bid);
        // ---- layer 3: + eb3, LN, residual, scatter
        gemm_layer(Ab, sW3, wt, lane, acc);

        // --- prefetch next tile (Ab no longer read by this warp; overlaps LN+writeback)
        {
            int tn = tile + tstep;
            if (tn < EDGE_TTILES){
                const float4* s4 = (const float4*)(ea + (size_t)tn * 16 * 128);
                #pragma unroll
                for (int rep = 0; rep < 4; rep++) pf[rep] = s4[tt + rep * 128];
                pviA = ei[tn*16 + g];       pvjA = ei[NEDGE + tn*16 + g];
                pviB = ei[tn*16 + g + 8];   pvjB = ei[NEDGE + tn*16 + g + 8];
            }
        }

        float s0=0.f,q0=0.f,s1=0.f,q1=0.f;
        #pragma unroll
        for (int nt = 0; nt < 4; nt++){
            int col = wt*32 + nt*8 + tig*2;
            acc[nt][0] += sB[128+col]; acc[nt][1] += sB[128+col+1];
            acc[nt][2] += sB[128+col]; acc[nt][3] += sB[128+col+1];
            s0 += acc[nt][0]+acc[nt][1]; q0 += acc[nt][0]*acc[nt][0]+acc[nt][1]*acc[nt][1];
            s1 += acc[nt][2]+acc[nt][3]; q1 += acc[nt][2]*acc[nt][2]+acc[nt][3]*acc[nt][3];
        }
        #pragma unroll
        for (int o = 1; o < 4; o <<= 1){
            s0 += __shfl_xor_sync(0xffffffffu, s0, o);
            q0 += __shfl_xor_sync(0xffffffffu, q0, o);
            s1 += __shfl_xor_sync(0xffffffffu, s1, o);
            q1 += __shfl_xor_sync(0xffffffffu, q1, o);
        }
        if (tig == 0){
            int ib = team*64 + wt*16;
            sRed[ib+g] = s0; sRed[ib+g+8] = s1;
            sRed[192+ib+g] = q0; sRed[192+ib+g+8] = q1;
        }
        TBAR(bid);
        float sumA=0.f,sqA=0.f,sumB=0.f,sqB=0.f;
        #pragma unroll
        for (int w2 = 0; w2 < 4; w2++){
            int ib = team*64 + w2*16;
            sumA += sRed[ib+g];   sqA += sRed[192+ib+g];
            sumB += sRed[ib+g+8]; sqB += sRed[192+ib+g+8];
        }
        float mA = sumA*(1.f/128.f), iA = rsqrtf(sqA*(1.f/128.f) - mA*mA + EPS_LN);
        float mB = sumB*(1.f/128.f), iB = rsqrtf(sqB*(1.f/128.f) - mB*mB + EPS_LN);
        #pragma unroll
        for (int nt = 0; nt < 4; nt++){
            int col = wt*32 + nt*8 + tig*2;
            float gm0 = sB[256+col], gm1 = sB[256+col+1];
            float bt0 = sB[384+col], bt1 = sB[384+col+1];
            float2 rA = *(const float2*)(ea + (size_t)eA*128 + col);
            float2 rB = *(const float2*)(ea + (size_t)eB*128 + col);
            float2 oA = { rA.x + (acc[nt][0]-mA)*iA*gm0 + bt0,
                          rA.y + (acc[nt][1]-mA)*iA*gm1 + bt1 };
            float2 oB = { rB.x + (acc[nt][2]-mB)*iB*gm0 + bt0,
                          rB.y + (acc[nt][3]-mB)*iB*gm1 + bt1 };
            *(float2*)(outE + (size_t)eA*128 + col) = oA;
            *(float2*)(outE + (size_t)eB*128 + col) = oB;
            asm volatile("red.global.add.v2.f32 [%0], {%1,%2};"
                         :: "l"(g_agg + (size_t)vjA*128 + col), "f"(oA.x), "f"(oA.y) : "memory");
            asm volatile("red.global.add.v2.f32 [%0], {%1,%2};"
                         :: "l"(g_agg + (size_t)vjB*128 + col), "f"(oB.x), "f"(oB.y) : "memory");
        }
    }
}

// ------------------------------------------------------------------ kernel 3
__global__ void __launch_bounds__(NTHREADS, 1) node_kernel(
    const float* __restrict__ x,
    const float* __restrict__ nw1, const float* __restrict__ nw2, const float* __restrict__ nw3,
    const float* __restrict__ nb2, const float* __restrict__ nb3,
    const float* __restrict__ nlg, const float* __restrict__ nlb,
    float* __restrict__ outX)
{
    extern __shared__ float sm[];
    float* sW1 = sm;
    float* sW2 = sm + 16384;
    float* sW3 = sm + 32768;
    float* sB  = sm + 49152;
    float* sRed= sm + 49664;
    float* sA  = sm + 50048;

    const int tid = threadIdx.x;
    load_wfrag(nw1 + 16384, sW1, tid, NTHREADS);
    load_wfrag(nw2,         sW2, tid, NTHREADS);
    load_wfrag(nw3,         sW3, tid, NTHREADS);
    if (tid < 128){
        sB[tid] = nb2[tid]; sB[128+tid] = nb3[tid]; sB[256+tid] = nlg[tid]; sB[384+tid] = nlb[tid];
    }
    __syncthreads();

    const int wid = tid >> 5, lane = tid & 31, team = wid >> 2, wt = wid & 3;
    const int g = lane >> 2, tig = lane & 3, tt = tid & 127, bid = 1 + team;
    float* Ab = sA + team * (16 * ASTRIDE);

    for (int tile = blockIdx.x * NTEAMS + team; tile < NODE_TTILES; tile += gridDim.x * NTEAMS){
        const int n0 = tile * 16;
        TBAR(bid);
        stage16(g_agg + (size_t)n0 * 128, Ab, tt);
        TBAR(bid);
        const int rA = n0 + g, rB = n0 + g + 8;

        // early gather of Pn rows (consumed after gemm1)
        float2 pnA[4], pnB[4];
        #pragma unroll
        for (int nt = 0; nt < 4; nt++){
            int col = wt*32 + nt*8 + tig*2;
            pnA[nt] = __ldg((const float2*)(g_Pn + (size_t)rA*128 + col));
            pnB[nt] = __ldg((const float2*)(g_Pn + (size_t)rB*128 + col));
        }

        float acc[4][4];
        gemm_layer(Ab, sW1, wt, lane, acc);
        TBAR(bid);
        #pragma unroll
        for (int nt = 0; nt < 4; nt++){
            int col = wt*32 + nt*8 + tig*2;
            float2 wA = { __uint_as_float(f2tf(sigl(acc[nt][0] + pnA[nt].x))),
                          __uint_as_float(f2tf(sigl(acc[nt][1] + pnA[nt].y))) };
            float2 wB = { __uint_as_float(f2tf(sigl(acc[nt][2] + pnB[nt].x))),
                          __uint_as_float(f2tf(sigl(acc[nt][3] + pnB[nt].y))) };
            *(float2*)(Ab +  g   *ASTRIDE + col) = wA;
            *(float2*)(Ab + (g+8)*ASTRIDE + col) = wB;
        }
        TBAR(bid);
        gemm_layer(Ab, sW2, wt, lane, acc);
        TBAR(bid);
        #pragma unroll
        for (int nt = 0; nt < 4; nt++){
            int col = wt*32 + nt*8 + tig*2;
            float b0 = sB[col], b1 = sB[col+1];
            float2 wA = { __uint_as_float(f2tf(sigl(acc[nt][0] + b0))),
                          __uint_as_float(f2tf(sigl(acc[nt][1] + b1))) };
            float2 wB = { __uint_as_float(f2tf(sigl(acc[nt][2] + b0))),
                          __uint_as_float(f2tf(sigl(acc[nt][3] + b1))) };
            *(float2*)(Ab +  g   *ASTRIDE + col) = wA;
            *(float2*)(Ab + (g+8)*ASTRIDE + col) = wB;
        }
        TBAR(bid);
        gemm_layer(Ab, sW3, wt, lane, acc);
        float s0=0.f,q0=0.f,s1=0.f,q1=0.f;
        #pragma unroll
        for (int nt = 0; nt < 4; nt++){
            int col = wt*32 + nt*8 + tig*2;
            acc[nt][0] += sB[128+col]; acc[nt][1] += sB[128+col+1];
            acc[nt][2] += sB[128+col]; acc[nt][3] += sB[128+col+1];
            s0 += acc[nt][0]+acc[nt][1]; q0 += acc[nt][0]*acc[nt][0]+acc[nt][1]*acc[nt][1];
            s1 += acc[nt][2]+acc[nt][3]; q1 += acc[nt][2]*acc[nt][2]+acc[nt][3]*acc[nt][3];
        }
        #pragma unroll
        for (int o = 1; o < 4; o <<= 1){
            s0 += __shfl_xor_sync(0xffffffffu, s0, o);
            q0 += __shfl_xor_sync(0xffffffffu, q0, o);
            s1 += __shfl_xor_sync(0xffffffffu, s1, o);
            q1 += __shfl_xor_sync(0xffffffffu, q1, o);
        }
        if (tig == 0){
            int ib = team*64 + wt*16;
            sRed[ib+g] = s0; sRed[ib+g+8] = s1;
            sRed[192+ib+g] = q0; sRed[192+ib+g+8] = q1;
        }
        TBAR(bid);
        float sumA=0.f,sqA=0.f,sumB=0.f,sqB=0.f;
        #pragma unroll
        for (int w2 = 0; w2 < 4; w2++){
            int ib = team*64 + w2*16;
            sumA += sRed[ib+g];   sqA += sRed[192+ib+g];
            sumB += sRed[ib+g+8]; sqB += sRed[192+ib+g+8];
        }
        float mA = sumA*(1.f/128.f), iA = rsqrtf(sqA*(1.f/128.f) - mA*mA + EPS_LN);
        float mB = sumB*(1.f/128.f), iB = rsqrtf(sqB*(1.f/128.f) - mB*mB + EPS_LN);
        #pragma unroll
        for (int nt = 0; nt < 4; nt++){
            int col = wt*32 + nt*8 + tig*2;
            float gm0 = sB[256+col], gm1 = sB[256+col+1];
            float bt0 = sB[384+col], bt1 = sB[384+col+1];
            float2 rxA = *(const float2*)(x + (size_t)rA*128 + col);
            float2 rxB = *(const float2*)(x + (size_t)rB*128 + col);
            float2 oA = { rxA.x + (acc[nt][0]-mA)*iA*gm0 + bt0,
                          rxA.y + (acc[nt][1]-mA)*iA*gm1 + bt1 };
            float2 oB = { rxB.x + (acc[nt][2]-mB)*iB*gm0 + bt0,
                          rxB.y + (acc[nt][3]-mB)*iB*gm1 + bt1 };
            *(float2*)(outX + (size_t)rA*128 + col) = oA;
            *(float2*)(outX + (size_t)rB*128 + col) = oB;
        }
    }
}

// ------------------------------------------------------------------ host
extern "C" void kernel_launch(void* const* d_in, const int* in_sizes, int n_in,
                              void* d_out, int out_size) {
    const float* x   = (const float*)d_in[0];
    const int*   ei  = (const int*)  d_in[1];
    const float* ea  = (const float*)d_in[2];
    const float* ew1 = (const float*)d_in[3];
    const float* eb1 = (const float*)d_in[4];
    const float* ew2 = (const float*)d_in[5];
    const float* eb2 = (const float*)d_in[6];
    const float* ew3 = (const float*)d_in[7];
    const float* eb3 = (const float*)d_in[8];
    const float* elg = (const float*)d_in[9];
    const float* elb = (const float*)d_in[10];
    const float* nw1 = (const float*)d_in[11];
    const float* nb1 = (const float*)d_in[12];
    const float* nw2 = (const float*)d_in[13];
    const float* nb2 = (const float*)d_in[14];
    const float* nw3 = (const float*)d_in[15];
    const float* nb3 = (const float*)d_in[16];
    const float* nlg = (const float*)d_in[17];
    const float* nlb = (const float*)d_in[18];

    float* outX = (float*)d_out;
    float* outE = outX + (size_t)NNODE * 128;

    const size_t smem_pre  = 55744u * 4u;   // 222976
    const size_t smem_main = 56384u * 4u;   // 225536
    cudaFuncSetAttribute(pre_kernel,  cudaFuncAttributeMaxDynamicSharedMemorySize, (int)smem_pre);
    cudaFuncSetAttribute(edge_kernel, cudaFuncAttributeMaxDynamicSharedMemorySize, (int)smem_main);
    cudaFuncSetAttribute(node_kernel, cudaFuncAttributeMaxDynamicSharedMemorySize, (int)smem_main);

    void* aggp = nullptr;
    cudaGetSymbolAddress(&aggp, g_agg);
    cudaMemsetAsync(aggp, 0, sizeof(float) * (size_t)NNODE * 128, 0);

    pre_kernel<<<152, NTHREADS, smem_pre>>>(x, ew1, eb1, nw1, nb1);
    edge_kernel<<<152, NTHREADS, smem_main>>>(ei, ea, ew1, ew2, ew3, eb2, eb3, elg, elb, outE);
    node_kernel<<<152, NTHREADS, smem_main>>>(x, nw1, nw2, nw3, nb2, nb3, nlg, nlb, outX);
}